// round 1
// baseline (speedup 1.0000x reference)
#include <cuda_runtime.h>
#include <math.h>

#define NB 4
#define NH 480
#define NW 640
#define NSEM 16
#define NC 20
#define MM 480
#define VRD 100
#define NZV 80
#define BANDLO 13
#define BANDN 12

// Scratch (device globals; no allocations allowed)
__device__ __align__(16) float g_vox0[NB][VRD][VRD][NZV];           // occupancy ch: [b][p1][p0][z]
__device__ __align__(16) float g_voxC[NB][VRD][VRD][BANDN][NSEM];   // sem chans, z-band only: [b][p1][p0][zb][s]
__device__ __align__(16) float g_compact[NB][18][VRD * VRD];        // clipped agent-view window [b][cc][p1*100+p0]
__device__ float g_pose[NB][4];                                     // cos_t, sin_t, tx, ty

// ---------------------------------------------------------------------------
__global__ void zero_kernel() {
    const int na = NB * VRD * VRD * NZV / 4;            // 800000 float4
    const int nb = NB * VRD * VRD * BANDN * NSEM / 4;   // 1920000 float4
    float4* a = reinterpret_cast<float4*>(&g_vox0[0][0][0][0]);
    float4* c = reinterpret_cast<float4*>(&g_voxC[0][0][0][0][0]);
    float4 z = make_float4(0.f, 0.f, 0.f, 0.f);
    int stride = gridDim.x * blockDim.x;
    for (int i = blockIdx.x * blockDim.x + threadIdx.x; i < na; i += stride) a[i] = z;
    for (int i = blockIdx.x * blockDim.x + threadIdx.x; i < nb; i += stride) c[i] = z;
}

// ---------------------------------------------------------------------------
__global__ void pose_kernel(const float* __restrict__ pose_obs,
                            const float* __restrict__ poses_last,
                            float* __restrict__ poses_out) {
    int b = threadIdx.x;
    if (b >= NB) return;
    const float R2D = 57.29577951308232f;
    float plx = poses_last[3 * b + 0];
    float ply = poses_last[3 * b + 1];
    float plo = poses_last[3 * b + 2];
    float dx = pose_obs[3 * b + 0];
    float dy = pose_obs[3 * b + 1];
    float dth = pose_obs[3 * b + 2];
    float r = __fdiv_rn(plo, R2D);
    float sr = sinf(r), cr = cosf(r);
    float yy = __fadd_rn(__fadd_rn(ply, __fmul_rn(dx, sr)), __fmul_rn(dy, cr));
    float xx = __fsub_rn(__fadd_rn(plx, __fmul_rn(dx, cr)), __fmul_rn(dy, sr));
    float oo = __fadd_rn(plo, __fmul_rn(dth, R2D));
    oo = __fadd_rn(fmodf(__fsub_rn(oo, 180.0f), 360.0f), 180.0f);
    oo = __fsub_rn(fmodf(__fadd_rn(oo, 180.0f), 360.0f), 180.0f);
    poses_out[3 * b + 0] = xx;
    poses_out[3 * b + 1] = yy;
    poses_out[3 * b + 2] = oo;
    // st_xy = -(xy*100/5 - 240)/240
    float stx = __fdiv_rn(-__fsub_rn(__fdiv_rn(__fmul_rn(xx, 100.0f), 5.0f), 240.0f), 240.0f);
    float sty = __fdiv_rn(-__fsub_rn(__fdiv_rn(__fmul_rn(yy, 100.0f), 5.0f), 240.0f), 240.0f);
    float tt = __fdiv_rn(__fmul_rn(__fsub_rn(90.0f, oo), 3.14159265358979323846f), 180.0f);
    g_pose[b][0] = cosf(tt);
    g_pose[b][1] = sinf(tt);
    g_pose[b][2] = stx;
    g_pose[b][3] = sty;
}

// ---------------------------------------------------------------------------
__global__ void splat_kernel(const float* __restrict__ obs, float focal) {
    int idx = blockIdx.x * blockDim.x + threadIdx.x;
    if (idx >= NB * NH * NW) return;
    int w = idx % NW;
    int t = idx / NW;
    int h = t % NH;
    int b = t / NH;

    size_t obs_b = (size_t)b * NC * NH * NW;
    size_t pix = (size_t)h * NW + w;
    float depth = obs[obs_b + (size_t)3 * NH * NW + pix];

    // X = (gx - xc)*depth/f ; Z = (gz - zc)*depth/f, gz = H-1-h
    float X = __fdiv_rn(__fmul_rn(__fsub_rn((float)w, 319.5f), depth), focal);
    float Z = __fdiv_rn(__fmul_rn(__fsub_rn((float)(NH - 1 - h), 239.5f), depth), focal);

    // pos0: ((X+250)/5 - 50)/100*2, then *50+50
    float t0 = __fdiv_rn(__fadd_rn(X, 250.0f), 5.0f);
    t0 = __fmul_rn(__fdiv_rn(__fsub_rn(t0, 50.0f), 100.0f), 2.0f);
    float pos0 = __fadd_rn(__fmul_rn(t0, 50.0f), 50.0f);
    // pos1: (depth/5 - 50)/100*2, then *50+50
    float t1 = __fdiv_rn(depth, 5.0f);
    t1 = __fmul_rn(__fdiv_rn(__fsub_rn(t1, 50.0f), 100.0f), 2.0f);
    float pos1 = __fadd_rn(__fmul_rn(t1, 50.0f), 50.0f);
    // pos2: ((Z+88)/5 - 32)/80*2, then *40+40
    float t2 = __fdiv_rn(__fadd_rn(Z, 88.0f), 5.0f);
    t2 = __fmul_rn(__fdiv_rn(__fsub_rn(t2, 32.0f), 80.0f), 2.0f);
    float pos2 = __fadd_rn(__fmul_rn(t2, 40.0f), 40.0f);

    float f0 = floorf(pos0), f1 = floorf(pos1), f2 = floorf(pos2);
    float wg0[2], wg1[2], wg2[2];
    int i0[2], i1[2], i2[2];
#pragma unroll
    for (int o = 0; o < 2; o++) {
        float p = f0 + (float)o;
        bool s = (p > 0.0f) && (p < 100.0f);
        wg0[o] = s ? (1.0f - fabsf(__fsub_rn(pos0, p))) : 0.0f;
        i0[o] = s ? (int)p : 0;
        p = f1 + (float)o;
        s = (p > 0.0f) && (p < 100.0f);
        wg1[o] = s ? (1.0f - fabsf(__fsub_rn(pos1, p))) : 0.0f;
        i1[o] = s ? (int)p : 0;
        p = f2 + (float)o;
        s = (p > 0.0f) && (p < 80.0f);
        wg2[o] = s ? (1.0f - fabsf(__fsub_rn(pos2, p))) : 0.0f;
        i2[o] = s ? (int)p : 0;
    }
    if ((wg0[0] == 0.f && wg0[1] == 0.f) ||
        (wg1[0] == 0.f && wg1[1] == 0.f) ||
        (wg2[0] == 0.f && wg2[1] == 0.f))
        return;

    bool band = ((wg2[0] > 0.f && i2[0] >= BANDLO && i2[0] < BANDLO + BANDN) ||
                 (wg2[1] > 0.f && i2[1] >= BANDLO && i2[1] < BANDLO + BANDN));
    float sem[NSEM];
    if (band) {
#pragma unroll
        for (int s = 0; s < NSEM; s++)
            sem[s] = obs[obs_b + (size_t)(4 + s) * NH * NW + pix];
    }

#pragma unroll
    for (int a = 0; a < 2; a++) {
        if (wg0[a] == 0.f) continue;
#pragma unroll
        for (int c = 0; c < 2; c++) {
            float wac = __fmul_rn(wg0[a], wg1[c]);
            if (wac == 0.f) continue;
#pragma unroll
            for (int e = 0; e < 2; e++) {
                float wt = __fmul_rn(wac, wg2[e]);
                if (wt == 0.f) continue;
                atomicAdd(&g_vox0[b][i1[c]][i0[a]][i2[e]], wt);
                int zb = i2[e] - BANDLO;
                if ((unsigned)zb < (unsigned)BANDN) {
                    float* dst = &g_voxC[b][i1[c]][i0[a]][zb][0];
#pragma unroll
                    for (int s = 0; s < NSEM; s++)
                        atomicAdd(dst + s, __fmul_rn(sem[s], wt));
                }
            }
        }
    }
}

// ---------------------------------------------------------------------------
__global__ void proj_kernel(float* __restrict__ fp_out) {
    int idx = blockIdx.x * blockDim.x + threadIdx.x;
    if (idx >= NB * VRD * VRD) return;
    int p0 = idx % VRD;
    int t = idx / VRD;
    int p1 = t % VRD;
    int b = t / VRD;

    const float4* v0 = reinterpret_cast<const float4*>(&g_vox0[b][p1][p0][0]);
    float s_all = 0.f, s_band = 0.f;
#pragma unroll
    for (int q = 0; q < NZV / 4; q++) {
        float4 v = v0[q];
        float r0 = rintf(v.x), r1 = rintf(v.y), r2 = rintf(v.z), r3 = rintf(v.w);
        s_all += r0 + r1 + r2 + r3;
        int z = q * 4;
        if (z + 0 >= BANDLO && z + 0 < BANDLO + BANDN) s_band += r0;
        if (z + 1 >= BANDLO && z + 1 < BANDLO + BANDN) s_band += r1;
        if (z + 2 >= BANDLO && z + 2 < BANDLO + BANDN) s_band += r2;
        if (z + 3 >= BANDLO && z + 3 < BANDLO + BANDN) s_band += r3;
    }

    float ssem[NSEM];
#pragma unroll
    for (int s = 0; s < NSEM; s++) ssem[s] = 0.f;
    const float4* vc = reinterpret_cast<const float4*>(&g_voxC[b][p1][p0][0][0]);
#pragma unroll
    for (int zb = 0; zb < BANDN; zb++) {
#pragma unroll
        for (int q = 0; q < NSEM / 4; q++) {
            float4 v = vc[zb * (NSEM / 4) + q];
            ssem[q * 4 + 0] += rintf(v.x);
            ssem[q * 4 + 1] += rintf(v.y);
            ssem[q * 4 + 2] += rintf(v.z);
            ssem[q * 4 + 3] += rintf(v.w);
        }
    }

    int sp = p1 * VRD + p0;
    float m = fminf(fmaxf(__fdiv_rn(s_band, 1.0f), 0.f), 1.f);
    g_compact[b][0][sp] = m;
    g_compact[b][1][sp] = fminf(fmaxf(__fdiv_rn(s_all, 1.0f), 0.f), 1.f);
    fp_out[(size_t)b * VRD * VRD + sp] = m;
#pragma unroll
    for (int s = 0; s < NSEM; s++)
        g_compact[b][2 + s][sp] = fminf(fmaxf(__fdiv_rn(ssem[s], 5.0f), 0.f), 1.f);
}

// ---------------------------------------------------------------------------
__global__ void xform_kernel(const float* __restrict__ maps_last,
                             float* __restrict__ map_out) {
    int idx = blockIdx.x * blockDim.x + threadIdx.x;
    if (idx >= NB * MM * MM) return;
    int w = idx % MM;
    int t = idx / MM;
    int h = t % MM;
    int b = t / MM;

    float ct = g_pose[b][0], sn = g_pose[b][1], tx = g_pose[b][2], ty = g_pose[b][3];
    const float step = 2.0f / 479.0f;
    float gx = __fsub_rn(__fmul_rn((float)w, step), 1.0f);
    float gy = __fsub_rn(__fmul_rn((float)h, step), 1.0f);
    // translation pass source coords
    float x = __fmul_rn(__fmul_rn(__fadd_rn(__fadd_rn(gx, tx), 1.0f), 0.5f), 479.0f);
    float y = __fmul_rn(__fmul_rn(__fadd_rn(__fadd_rn(gy, ty), 1.0f), 0.5f), 479.0f);
    float x0 = floorf(x), y0 = floorf(y);
    float wxv[2] = { __fsub_rn(__fadd_rn(x0, 1.0f), x), __fsub_rn(x, x0) };
    float wyv[2] = { __fsub_rn(__fadd_rn(y0, 1.0f), y), __fsub_rn(y, y0) };

    float pw[16];
    int po[16];
    bool any = false;
#pragma unroll
    for (int i = 0; i < 2; i++) {
        float qxf = x0 + (float)i;
#pragma unroll
        for (int j = 0; j < 2; j++) {
            float qyf = y0 + (float)j;
            float wk = __fmul_rn(wxv[i], wyv[j]);
            int base = (i * 2 + j) * 4;
            bool v = (qxf >= 0.f) && (qxf <= 479.f) && (qyf >= 0.f) && (qyf <= 479.f) && (wk > 0.f);
            float rx0 = 0.f, ry0 = 0.f;
            float wrx[2] = {0.f, 0.f}, wry[2] = {0.f, 0.f};
            if (v) {
                // rotation pass evaluated at integer pixel (qyf, qxf)
                float gqx = __fsub_rn(__fmul_rn(qxf, step), 1.0f);
                float gqy = __fsub_rn(__fmul_rn(qyf, step), 1.0f);
                float r0 = __fsub_rn(__fmul_rn(gqx, ct), __fmul_rn(gqy, sn));
                float r1 = __fadd_rn(__fmul_rn(gqx, sn), __fmul_rn(gqy, ct));
                float rx = __fmul_rn(__fmul_rn(__fadd_rn(r0, 1.0f), 0.5f), 479.0f);
                float ry = __fmul_rn(__fmul_rn(__fadd_rn(r1, 1.0f), 0.5f), 479.0f);
                rx0 = floorf(rx);
                ry0 = floorf(ry);
                wrx[0] = __fsub_rn(__fadd_rn(rx0, 1.0f), rx);
                wrx[1] = __fsub_rn(rx, rx0);
                wry[0] = __fsub_rn(__fadd_rn(ry0, 1.0f), ry);
                wry[1] = __fsub_rn(ry, ry0);
            }
#pragma unroll
            for (int di = 0; di < 2; di++) {
#pragma unroll
                for (int dj = 0; dj < 2; dj++) {
                    float fx = rx0 + (float)di;
                    float fy = ry0 + (float)dj;
                    // agent-view nonzero window: x in [190,290), y in [240,340) (subset of [0,479])
                    bool inr = v && (fx >= 190.f) && (fx <= 289.f) && (fy >= 240.f) && (fy <= 339.f);
                    float wgt = inr ? __fmul_rn(wk, __fmul_rn(wrx[di], wry[dj])) : 0.f;
                    int off = inr ? (((int)fy - 240) * VRD + ((int)fx - 190)) : 0;
                    int slot = base + di * 2 + dj;
                    pw[slot] = wgt;
                    po[slot] = off;
                    any = any || (wgt != 0.f);
                }
            }
        }
    }

    size_t plane = (size_t)MM * MM;
    size_t pixoff = (size_t)b * NC * plane + (size_t)h * MM + w;
    if (!any) {
        // translated == 0 everywhere here -> max(maps_last, 0) ... but maps_last in [0,1], and
        // reference takes elementwise max with translated==0: maps_last >= 0, so plain copy.
#pragma unroll
        for (int c = 0; c < NC; c++)
            map_out[pixoff + (size_t)c * plane] = fmaxf(maps_last[pixoff + (size_t)c * plane], 0.0f);
        return;
    }
    // channels 2,3 are always zero in agent_view -> translated==0
    map_out[pixoff + 2 * plane] = fmaxf(maps_last[pixoff + 2 * plane], 0.0f);
    map_out[pixoff + 3 * plane] = fmaxf(maps_last[pixoff + 3 * plane], 0.0f);
    const float* cb = &g_compact[b][0][0];
#pragma unroll
    for (int cc = 0; cc < 18; cc++) {
        float vsum = 0.f;
#pragma unroll
        for (int k = 0; k < 16; k++)
            vsum += pw[k] * cb[cc * (VRD * VRD) + po[k]];
        int oc = (cc < 2) ? cc : cc + 2;
        map_out[pixoff + (size_t)oc * plane] = fmaxf(maps_last[pixoff + (size_t)oc * plane], vsum);
    }
}

// ---------------------------------------------------------------------------
extern "C" void kernel_launch(void* const* d_in, const int* in_sizes, int n_in,
                              void* d_out, int out_size) {
    const float* obs = (const float*)d_in[0];
    const float* pose_obs = (const float*)d_in[1];
    const float* maps_last = (const float*)d_in[2];
    const float* poses_last = (const float*)d_in[3];

    float* out = (float*)d_out;
    float* fp_out = out;                                         // 4*1*100*100 = 40000
    float* map_out = out + (size_t)NB * VRD * VRD;               // 4*20*480*480
    float* poses_out = map_out + (size_t)NB * NC * MM * MM;      // 4*3

    // focal length, computed in double on host exactly like the reference
    float focal = (float)((NW / 2.0) / tan((79.0 / 2.0) * M_PI / 180.0));

    zero_kernel<<<1024, 256>>>();
    pose_kernel<<<1, 32>>>(pose_obs, poses_last, poses_out);
    int npix = NB * NH * NW;
    splat_kernel<<<(npix + 255) / 256, 256>>>(obs, focal);
    int nproj = NB * VRD * VRD;
    proj_kernel<<<(nproj + 255) / 256, 256>>>(fp_out);
    int nx = NB * MM * MM;
    xform_kernel<<<(nx + 127) / 128, 128>>>(maps_last, map_out);
}

// round 2
// speedup vs baseline: 2.0669x; 2.0669x over previous
#include <cuda_runtime.h>
#include <math.h>

#define NB 4
#define NH 480
#define NW 640
#define NSEM 16
#define NC 20
#define MM 480
#define VRD 100
#define NZV 80
#define BANDLO 13
#define BANDN 12

// Scratch (device globals; no allocations allowed)
__device__ __align__(16) float g_vox0[NB][VRD][VRD][NZV];           // occupancy ch: [b][p1][p0][z]
__device__ __align__(16) float g_voxC[NB][VRD][VRD][BANDN][NSEM];   // sem chans, z-band only
__device__ __align__(16) float g_compact[NB][18][VRD * VRD];        // clipped agent-view window
__device__ float g_pose[NB][4];                                     // cos_t, sin_t, tx, ty

// Vector global reductions (sm_90+): fewer atomic lanes, same traffic
__device__ __forceinline__ void red_add_v4(float* p, float a, float b, float c, float d) {
    asm volatile("red.global.add.v4.f32 [%0], {%1, %2, %3, %4};"
                 :: "l"(p), "f"(a), "f"(b), "f"(c), "f"(d) : "memory");
}
__device__ __forceinline__ void red_add_v2(float* p, float a, float b) {
    asm volatile("red.global.add.v2.f32 [%0], {%1, %2};"
                 :: "l"(p), "f"(a), "f"(b) : "memory");
}

// ---------------------------------------------------------------------------
__global__ void zero_kernel() {
    const int na = NB * VRD * VRD * NZV / 4;            // 800000 float4
    const int nb = NB * VRD * VRD * BANDN * NSEM / 4;   // 1920000 float4
    float4* a = reinterpret_cast<float4*>(&g_vox0[0][0][0][0]);
    float4* c = reinterpret_cast<float4*>(&g_voxC[0][0][0][0][0]);
    float4 z = make_float4(0.f, 0.f, 0.f, 0.f);
    int stride = gridDim.x * blockDim.x;
    for (int i = blockIdx.x * blockDim.x + threadIdx.x; i < na; i += stride) a[i] = z;
    for (int i = blockIdx.x * blockDim.x + threadIdx.x; i < nb; i += stride) c[i] = z;
}

// ---------------------------------------------------------------------------
__global__ void pose_kernel(const float* __restrict__ pose_obs,
                            const float* __restrict__ poses_last,
                            float* __restrict__ poses_out) {
    int b = threadIdx.x;
    if (b >= NB) return;
    const float R2D = 57.29577951308232f;
    float plx = poses_last[3 * b + 0];
    float ply = poses_last[3 * b + 1];
    float plo = poses_last[3 * b + 2];
    float dx = pose_obs[3 * b + 0];
    float dy = pose_obs[3 * b + 1];
    float dth = pose_obs[3 * b + 2];
    float r = __fdiv_rn(plo, R2D);
    float sr = sinf(r), cr = cosf(r);
    float yy = __fadd_rn(__fadd_rn(ply, __fmul_rn(dx, sr)), __fmul_rn(dy, cr));
    float xx = __fsub_rn(__fadd_rn(plx, __fmul_rn(dx, cr)), __fmul_rn(dy, sr));
    float oo = __fadd_rn(plo, __fmul_rn(dth, R2D));
    oo = __fadd_rn(fmodf(__fsub_rn(oo, 180.0f), 360.0f), 180.0f);
    oo = __fsub_rn(fmodf(__fadd_rn(oo, 180.0f), 360.0f), 180.0f);
    poses_out[3 * b + 0] = xx;
    poses_out[3 * b + 1] = yy;
    poses_out[3 * b + 2] = oo;
    float stx = __fdiv_rn(-__fsub_rn(__fdiv_rn(__fmul_rn(xx, 100.0f), 5.0f), 240.0f), 240.0f);
    float sty = __fdiv_rn(-__fsub_rn(__fdiv_rn(__fmul_rn(yy, 100.0f), 5.0f), 240.0f), 240.0f);
    float tt = __fdiv_rn(__fmul_rn(__fsub_rn(90.0f, oo), 3.14159265358979323846f), 180.0f);
    g_pose[b][0] = cosf(tt);
    g_pose[b][1] = sinf(tt);
    g_pose[b][2] = stx;
    g_pose[b][3] = sty;
}

// ---------------------------------------------------------------------------
__global__ void splat_kernel(const float* __restrict__ obs, float focal) {
    int idx = blockIdx.x * blockDim.x + threadIdx.x;
    if (idx >= NB * NH * NW) return;
    int w = idx % NW;
    int t = idx / NW;
    int h = t % NH;
    int b = t / NH;

    size_t obs_b = (size_t)b * NC * NH * NW;
    size_t pix = (size_t)h * NW + w;
    float depth = obs[obs_b + (size_t)3 * NH * NW + pix];

    float X = __fdiv_rn(__fmul_rn(__fsub_rn((float)w, 319.5f), depth), focal);
    float Z = __fdiv_rn(__fmul_rn(__fsub_rn((float)(NH - 1 - h), 239.5f), depth), focal);

    float t0 = __fdiv_rn(__fadd_rn(X, 250.0f), 5.0f);
    t0 = __fmul_rn(__fdiv_rn(__fsub_rn(t0, 50.0f), 100.0f), 2.0f);
    float pos0 = __fadd_rn(__fmul_rn(t0, 50.0f), 50.0f);
    float t1 = __fdiv_rn(depth, 5.0f);
    t1 = __fmul_rn(__fdiv_rn(__fsub_rn(t1, 50.0f), 100.0f), 2.0f);
    float pos1 = __fadd_rn(__fmul_rn(t1, 50.0f), 50.0f);
    float t2 = __fdiv_rn(__fadd_rn(Z, 88.0f), 5.0f);
    t2 = __fmul_rn(__fdiv_rn(__fsub_rn(t2, 32.0f), 80.0f), 2.0f);
    float pos2 = __fadd_rn(__fmul_rn(t2, 40.0f), 40.0f);

    float f0 = floorf(pos0), f1 = floorf(pos1), f2 = floorf(pos2);
    float wg0[2], wg1[2], wg2[2];
    int i0[2], i1[2], i2[2];
#pragma unroll
    for (int o = 0; o < 2; o++) {
        float p = f0 + (float)o;
        bool s = (p > 0.0f) && (p < 100.0f);
        wg0[o] = s ? (1.0f - fabsf(__fsub_rn(pos0, p))) : 0.0f;
        i0[o] = s ? (int)p : 0;
        p = f1 + (float)o;
        s = (p > 0.0f) && (p < 100.0f);
        wg1[o] = s ? (1.0f - fabsf(__fsub_rn(pos1, p))) : 0.0f;
        i1[o] = s ? (int)p : 0;
        p = f2 + (float)o;
        s = (p > 0.0f) && (p < 80.0f);
        wg2[o] = s ? (1.0f - fabsf(__fsub_rn(pos2, p))) : 0.0f;
        i2[o] = s ? (int)p : 0;
    }
    if ((wg0[0] == 0.f && wg0[1] == 0.f) ||
        (wg1[0] == 0.f && wg1[1] == 0.f) ||
        (wg2[0] == 0.f && wg2[1] == 0.f))
        return;

    bool band = ((wg2[0] > 0.f && i2[0] >= BANDLO && i2[0] < BANDLO + BANDN) ||
                 (wg2[1] > 0.f && i2[1] >= BANDLO && i2[1] < BANDLO + BANDN));
    float sem[NSEM];
    if (band) {
#pragma unroll
        for (int s = 0; s < NSEM; s++)
            sem[s] = obs[obs_b + (size_t)(4 + s) * NH * NW + pix];
    }

    bool zpair = (wg2[0] > 0.f) && (wg2[1] > 0.f);   // i2[1] == i2[0]+1
    bool zalign = zpair && ((i2[0] & 1) == 0);       // 8B-aligned pair for v2 red

#pragma unroll
    for (int a = 0; a < 2; a++) {
        if (wg0[a] == 0.f) continue;
#pragma unroll
        for (int c = 0; c < 2; c++) {
            float wac = __fmul_rn(wg0[a], wg1[c]);
            if (wac == 0.f) continue;

            float wz0 = __fmul_rn(wac, wg2[0]);
            float wz1 = __fmul_rn(wac, wg2[1]);
            float* v0base = &g_vox0[b][i1[c]][i0[a]][0];
            if (zalign) {
                red_add_v2(v0base + i2[0], wz0, wz1);
            } else {
                if (wg2[0] > 0.f) atomicAdd(v0base + i2[0], wz0);
                if (wg2[1] > 0.f) atomicAdd(v0base + i2[1], wz1);
            }

#pragma unroll
            for (int e = 0; e < 2; e++) {
                float wt = (e == 0) ? wz0 : wz1;
                if (wt == 0.f) continue;
                int zb = i2[e] - BANDLO;
                if ((unsigned)zb < (unsigned)BANDN) {
                    float* dst = &g_voxC[b][i1[c]][i0[a]][zb][0];
#pragma unroll
                    for (int q = 0; q < 4; q++)
                        red_add_v4(dst + q * 4,
                                   __fmul_rn(sem[q * 4 + 0], wt),
                                   __fmul_rn(sem[q * 4 + 1], wt),
                                   __fmul_rn(sem[q * 4 + 2], wt),
                                   __fmul_rn(sem[q * 4 + 3], wt));
                }
            }
        }
    }
}

// ---------------------------------------------------------------------------
// 4 lanes cooperate per cell: lane L reads vox0 float4's L,L+4,... and voxC
// z-bands L, L+4, L+8; partials combined with shfl_xor within the 4-lane group.
__global__ void proj_kernel(float* __restrict__ fp_out) {
    int tid = blockIdx.x * blockDim.x + threadIdx.x;
    int cell = tid >> 2;
    int lane = tid & 3;
    if (cell >= NB * VRD * VRD) return;
    int p0 = cell % VRD;
    int t = cell / VRD;
    int p1 = t % VRD;
    int b = t / VRD;

    const float4* v0 = reinterpret_cast<const float4*>(&g_vox0[b][p1][p0][0]);
    float s_all = 0.f, s_band = 0.f;
#pragma unroll
    for (int q0 = 0; q0 < NZV / 16; q0++) {
        int q = q0 * 4 + lane;
        float4 v = v0[q];
        float r0 = rintf(v.x), r1 = rintf(v.y), r2 = rintf(v.z), r3 = rintf(v.w);
        s_all += r0 + r1 + r2 + r3;
        int z = q * 4;
        if (z + 0 >= BANDLO && z + 0 < BANDLO + BANDN) s_band += r0;
        if (z + 1 >= BANDLO && z + 1 < BANDLO + BANDN) s_band += r1;
        if (z + 2 >= BANDLO && z + 2 < BANDLO + BANDN) s_band += r2;
        if (z + 3 >= BANDLO && z + 3 < BANDLO + BANDN) s_band += r3;
    }

    float ssem[NSEM];
#pragma unroll
    for (int s = 0; s < NSEM; s++) ssem[s] = 0.f;
    const float4* vc = reinterpret_cast<const float4*>(&g_voxC[b][p1][p0][0][0]);
#pragma unroll
    for (int zb0 = 0; zb0 < BANDN / 4; zb0++) {
        int zb = zb0 * 4 + lane;
#pragma unroll
        for (int q = 0; q < NSEM / 4; q++) {
            float4 v = vc[zb * (NSEM / 4) + q];
            ssem[q * 4 + 0] += rintf(v.x);
            ssem[q * 4 + 1] += rintf(v.y);
            ssem[q * 4 + 2] += rintf(v.z);
            ssem[q * 4 + 3] += rintf(v.w);
        }
    }

#pragma unroll
    for (int off = 1; off < 4; off <<= 1) {
        s_all += __shfl_xor_sync(0xffffffffu, s_all, off);
        s_band += __shfl_xor_sync(0xffffffffu, s_band, off);
#pragma unroll
        for (int s = 0; s < NSEM; s++)
            ssem[s] += __shfl_xor_sync(0xffffffffu, ssem[s], off);
    }

    if (lane == 0) {
        int sp = p1 * VRD + p0;
        float m = fminf(fmaxf(__fdiv_rn(s_band, 1.0f), 0.f), 1.f);
        g_compact[b][0][sp] = m;
        g_compact[b][1][sp] = fminf(fmaxf(__fdiv_rn(s_all, 1.0f), 0.f), 1.f);
        fp_out[(size_t)b * VRD * VRD + sp] = m;
#pragma unroll
        for (int s = 0; s < NSEM; s++)
            g_compact[b][2 + s][sp] = fminf(fmaxf(__fdiv_rn(ssem[s], 5.0f), 0.f), 1.f);
    }
}

// ---------------------------------------------------------------------------
__global__ void xform_kernel(const float* __restrict__ maps_last,
                             float* __restrict__ map_out) {
    int idx = blockIdx.x * blockDim.x + threadIdx.x;
    if (idx >= NB * MM * MM) return;
    int w = idx % MM;
    int t = idx / MM;
    int h = t % MM;
    int b = t / MM;

    float ct = g_pose[b][0], sn = g_pose[b][1], tx = g_pose[b][2], ty = g_pose[b][3];
    const float step = 2.0f / 479.0f;
    float gx = __fsub_rn(__fmul_rn((float)w, step), 1.0f);
    float gy = __fsub_rn(__fmul_rn((float)h, step), 1.0f);
    float x = __fmul_rn(__fmul_rn(__fadd_rn(__fadd_rn(gx, tx), 1.0f), 0.5f), 479.0f);
    float y = __fmul_rn(__fmul_rn(__fadd_rn(__fadd_rn(gy, ty), 1.0f), 0.5f), 479.0f);
    float x0 = floorf(x), y0 = floorf(y);
    float wxv[2] = { __fsub_rn(__fadd_rn(x0, 1.0f), x), __fsub_rn(x, x0) };
    float wyv[2] = { __fsub_rn(__fadd_rn(y0, 1.0f), y), __fsub_rn(y, y0) };

    float pw[16];
    int po[16];
    bool any = false;
#pragma unroll
    for (int i = 0; i < 2; i++) {
        float qxf = x0 + (float)i;
#pragma unroll
        for (int j = 0; j < 2; j++) {
            float qyf = y0 + (float)j;
            float wk = __fmul_rn(wxv[i], wyv[j]);
            int base = (i * 2 + j) * 4;
            bool v = (qxf >= 0.f) && (qxf <= 479.f) && (qyf >= 0.f) && (qyf <= 479.f) && (wk > 0.f);
            float rx0 = 0.f, ry0 = 0.f;
            float wrx[2] = {0.f, 0.f}, wry[2] = {0.f, 0.f};
            if (v) {
                float gqx = __fsub_rn(__fmul_rn(qxf, step), 1.0f);
                float gqy = __fsub_rn(__fmul_rn(qyf, step), 1.0f);
                float r0 = __fsub_rn(__fmul_rn(gqx, ct), __fmul_rn(gqy, sn));
                float r1 = __fadd_rn(__fmul_rn(gqx, sn), __fmul_rn(gqy, ct));
                float rx = __fmul_rn(__fmul_rn(__fadd_rn(r0, 1.0f), 0.5f), 479.0f);
                float ry = __fmul_rn(__fmul_rn(__fadd_rn(r1, 1.0f), 0.5f), 479.0f);
                rx0 = floorf(rx);
                ry0 = floorf(ry);
                wrx[0] = __fsub_rn(__fadd_rn(rx0, 1.0f), rx);
                wrx[1] = __fsub_rn(rx, rx0);
                wry[0] = __fsub_rn(__fadd_rn(ry0, 1.0f), ry);
                wry[1] = __fsub_rn(ry, ry0);
            }
#pragma unroll
            for (int di = 0; di < 2; di++) {
#pragma unroll
                for (int dj = 0; dj < 2; dj++) {
                    float fx = rx0 + (float)di;
                    float fy = ry0 + (float)dj;
                    bool inr = v && (fx >= 190.f) && (fx <= 289.f) && (fy >= 240.f) && (fy <= 339.f);
                    float wgt = inr ? __fmul_rn(wk, __fmul_rn(wrx[di], wry[dj])) : 0.f;
                    int off = inr ? (((int)fy - 240) * VRD + ((int)fx - 190)) : 0;
                    int slot = base + di * 2 + dj;
                    pw[slot] = wgt;
                    po[slot] = off;
                    any = any || (wgt != 0.f);
                }
            }
        }
    }

    size_t plane = (size_t)MM * MM;
    size_t pixoff = (size_t)b * NC * plane + (size_t)h * MM + w;
    if (!any) {
#pragma unroll
        for (int c = 0; c < NC; c++)
            map_out[pixoff + (size_t)c * plane] = fmaxf(maps_last[pixoff + (size_t)c * plane], 0.0f);
        return;
    }
    map_out[pixoff + 2 * plane] = fmaxf(maps_last[pixoff + 2 * plane], 0.0f);
    map_out[pixoff + 3 * plane] = fmaxf(maps_last[pixoff + 3 * plane], 0.0f);
    const float* cb = &g_compact[b][0][0];
#pragma unroll
    for (int cc = 0; cc < 18; cc++) {
        float vsum = 0.f;
#pragma unroll
        for (int k = 0; k < 16; k++)
            vsum += pw[k] * cb[cc * (VRD * VRD) + po[k]];
        int oc = (cc < 2) ? cc : cc + 2;
        map_out[pixoff + (size_t)oc * plane] = fmaxf(maps_last[pixoff + (size_t)oc * plane], vsum);
    }
}

// ---------------------------------------------------------------------------
extern "C" void kernel_launch(void* const* d_in, const int* in_sizes, int n_in,
                              void* d_out, int out_size) {
    const float* obs = (const float*)d_in[0];
    const float* pose_obs = (const float*)d_in[1];
    const float* maps_last = (const float*)d_in[2];
    const float* poses_last = (const float*)d_in[3];

    float* out = (float*)d_out;
    float* fp_out = out;                                         // 4*1*100*100
    float* map_out = out + (size_t)NB * VRD * VRD;               // 4*20*480*480
    float* poses_out = map_out + (size_t)NB * NC * MM * MM;      // 4*3

    float focal = (float)((NW / 2.0) / tan((79.0 / 2.0) * M_PI / 180.0));

    zero_kernel<<<1024, 256>>>();
    pose_kernel<<<1, 32>>>(pose_obs, poses_last, poses_out);
    int npix = NB * NH * NW;
    splat_kernel<<<(npix + 255) / 256, 256>>>(obs, focal);
    int nproj = NB * VRD * VRD * 4;
    proj_kernel<<<(nproj + 255) / 256, 256>>>(fp_out);
    int nx = NB * MM * MM;
    xform_kernel<<<(nx + 255) / 256, 256>>>(maps_last, map_out);
}